// round 1
// baseline (speedup 1.0000x reference)
#include <cuda_runtime.h>
#include <math.h>

#define BATCH 2048
#define TT 64
#define EE 256
#define SCALE 0.125f

// ---------------- attention kernel ----------------
#define QT_PITCH 68   // 64 q padded (floats)
#define S_PITCH  65

#define SM_QT (EE * QT_PITCH)
#define SM_KT (EE * QT_PITCH)
#define SM_V  (TT * EE)
#define SM_S  (TT * S_PITCH)
#define ATTN_SMEM_BYTES ((SM_QT + SM_KT + SM_V + SM_S) * 4)

__global__ __launch_bounds__(256, 1)
void attn_kernel(const float* __restrict__ Qg, const float* __restrict__ Kg,
                 const float* __restrict__ Vg, float* __restrict__ Ag)
{
    extern __shared__ float sm[];
    float* QT = sm;                 // [EE][QT_PITCH]  (e-major, q inner)
    float* KT = QT + SM_QT;         // [EE][QT_PITCH]
    float* Vv = KT + SM_KT;         // [TT][EE]
    float* Ss = Vv + SM_V;          // [TT][S_PITCH]

    const int tid = threadIdx.x;
    const int b   = blockIdx.x;
    const size_t base = (size_t)b * TT * EE;
    const float* qb = Qg + base;
    const float* kb = Kg + base;
    const float* vb = Vg + base;

    // Load Q,K transposed (e rows, q cols) and V row-major. blockDim == EE == 256,
    // so each thread owns e = tid; iterate over the 64 rows. Global reads coalesced.
    #pragma unroll 4
    for (int i = 0; i < TT; ++i) {
        QT[tid * QT_PITCH + i] = qb[i * EE + tid];
        KT[tid * QT_PITCH + i] = kb[i * EE + tid];
        Vv[i * EE + tid]       = vb[i * EE + tid];
    }
    __syncthreads();

    const int tx = tid & 15;   // k-group (4 cols)
    const int ty = tid >> 4;   // q-group (4 rows)

    // ---- S = Q @ K^T  (64x64), 4x4 register tile per thread ----
    float acc[4][4];
    #pragma unroll
    for (int i = 0; i < 4; ++i)
        #pragma unroll
        for (int j = 0; j < 4; ++j) acc[i][j] = 0.0f;

    const float4* QT4 = (const float4*)QT;
    const float4* KT4 = (const float4*)KT;
    #pragma unroll 4
    for (int e = 0; e < EE; ++e) {
        float4 qv = QT4[e * (QT_PITCH / 4) + ty];
        float4 kv = KT4[e * (QT_PITCH / 4) + tx];
        const float qa[4] = {qv.x, qv.y, qv.z, qv.w};
        const float ka[4] = {kv.x, kv.y, kv.z, kv.w};
        #pragma unroll
        for (int i = 0; i < 4; ++i)
            #pragma unroll
            for (int j = 0; j < 4; ++j)
                acc[i][j] += qa[i] * ka[j];
    }

    // store S to smem
    #pragma unroll
    for (int i = 0; i < 4; ++i)
        #pragma unroll
        for (int j = 0; j < 4; ++j)
            Ss[(ty * 4 + i) * S_PITCH + tx * 4 + j] = acc[i][j];
    __syncthreads();

    // ---- softmax over rows (each warp handles 8 rows; 2 cols per lane) ----
    const int warp = tid >> 5, lane = tid & 31;
    #pragma unroll
    for (int rr = 0; rr < 8; ++rr) {
        const int r = warp * 8 + rr;
        float v1 = Ss[r * S_PITCH + lane]      * SCALE;
        float v2 = Ss[r * S_PITCH + lane + 32] * SCALE;
        float m = fmaxf(v1, v2);
        #pragma unroll
        for (int o = 16; o > 0; o >>= 1)
            m = fmaxf(m, __shfl_xor_sync(0xffffffffu, m, o));
        float e1 = expf(v1 - m);
        float e2 = expf(v2 - m);
        float s = e1 + e2;
        #pragma unroll
        for (int o = 16; o > 0; o >>= 1)
            s += __shfl_xor_sync(0xffffffffu, s, o);
        float inv = 1.0f / s;
        Ss[r * S_PITCH + lane]      = e1 * inv;
        Ss[r * S_PITCH + lane + 32] = e2 * inv;
    }
    __syncthreads();

    // ---- A = S @ V  (64x256): each thread computes 4 q-rows x 16 e-cols ----
    float accA[4][4][4];   // [i(q)][eb][j(e)]
    #pragma unroll
    for (int i = 0; i < 4; ++i)
        #pragma unroll
        for (int eb = 0; eb < 4; ++eb)
            #pragma unroll
            for (int j = 0; j < 4; ++j) accA[i][eb][j] = 0.0f;

    const float4* V4 = (const float4*)Vv;
    #pragma unroll 2
    for (int k = 0; k < TT; ++k) {
        float vvf[4][4];
        #pragma unroll
        for (int eb = 0; eb < 4; ++eb) {
            float4 vv = V4[k * (EE / 4) + eb * 16 + tx];
            vvf[eb][0] = vv.x; vvf[eb][1] = vv.y; vvf[eb][2] = vv.z; vvf[eb][3] = vv.w;
        }
        #pragma unroll
        for (int i = 0; i < 4; ++i) {
            const float sv = Ss[(ty * 4 + i) * S_PITCH + k];
            #pragma unroll
            for (int eb = 0; eb < 4; ++eb)
                #pragma unroll
                for (int j = 0; j < 4; ++j)
                    accA[i][eb][j] += sv * vvf[eb][j];
        }
    }

    // store attention (coalesced float4 per eb-block)
    float* ab = Ag + base;
    #pragma unroll
    for (int i = 0; i < 4; ++i) {
        #pragma unroll
        for (int eb = 0; eb < 4; ++eb) {
            float4 o = make_float4(accA[i][eb][0], accA[i][eb][1],
                                   accA[i][eb][2], accA[i][eb][3]);
            *(float4*)&ab[(ty * 4 + i) * EE + eb * 64 + tx * 4] = o;
        }
    }
}

// ---------------- feed-forward GEMM kernel ----------------
// out[2048,256] = relu( (attn+query)[2048,16384] @ W^T[16384,256] + b )
#define FK  16384
#define FBM 64
#define FBN 64
#define FBK 32

__device__ __forceinline__ float4 f4add(float4 a, float4 b) {
    return make_float4(a.x + b.x, a.y + b.y, a.z + b.z, a.w + b.w);
}

__global__ __launch_bounds__(256, 1)
void ff_kernel(const float* __restrict__ attn, const float* __restrict__ query,
               const float* __restrict__ Wg, const float* __restrict__ bias,
               float* __restrict__ out)
{
    __shared__ float Xs[FBK][FBM + 4];   // [k][m]
    __shared__ float Ws[FBK][FBN + 4];   // [k][n]

    const int tid = threadIdx.x;
    const int tx = tid & 15;   // n-group
    const int ty = tid >> 4;   // m-group
    const int m0 = blockIdx.x * FBM;
    const int n0 = blockIdx.y * FBN;

    // loader mapping: each thread loads float4 at (row lm and lm+32, f4-col lkc)
    const int lm  = tid >> 3;  // 0..31
    const int lkc = tid & 7;   // 0..7

    const float* xa = attn  + (size_t)(m0 + lm) * FK + lkc * 4;
    const float* xq = query + (size_t)(m0 + lm) * FK + lkc * 4;
    const float* wp = Wg    + (size_t)(n0 + lm) * FK + lkc * 4;
    const size_t half = (size_t)32 * FK;

    float acc[4][4];
    #pragma unroll
    for (int i = 0; i < 4; ++i)
        #pragma unroll
        for (int j = 0; j < 4; ++j) acc[i][j] = 0.0f;

    // prologue: stage tile k0=0 into registers
    float4 xA0 = f4add(*(const float4*)(xa), *(const float4*)(xq));
    float4 xA1 = f4add(*(const float4*)(xa + half), *(const float4*)(xq + half));
    float4 wA0 = *(const float4*)(wp);
    float4 wA1 = *(const float4*)(wp + half);

    for (int k0 = 0; k0 < FK; k0 += FBK) {
        // commit staged registers to smem (transposed)
        const float* x0 = (const float*)&xA0;
        const float* x1 = (const float*)&xA1;
        const float* w0 = (const float*)&wA0;
        const float* w1 = (const float*)&wA1;
        #pragma unroll
        for (int i = 0; i < 4; ++i) {
            Xs[lkc * 4 + i][lm]      = x0[i];
            Xs[lkc * 4 + i][lm + 32] = x1[i];
            Ws[lkc * 4 + i][lm]      = w0[i];
            Ws[lkc * 4 + i][lm + 32] = w1[i];
        }
        __syncthreads();

        // prefetch next tile (latency hidden behind compute)
        if (k0 + FBK < FK) {
            const int kn = k0 + FBK;
            xA0 = f4add(*(const float4*)(xa + kn), *(const float4*)(xq + kn));
            xA1 = f4add(*(const float4*)(xa + half + kn), *(const float4*)(xq + half + kn));
            wA0 = *(const float4*)(wp + kn);
            wA1 = *(const float4*)(wp + half + kn);
        }

        // compute
        #pragma unroll 8
        for (int k = 0; k < FBK; ++k) {
            float4 xm = *(const float4*)&Xs[k][ty * 4];
            float4 wn = *(const float4*)&Ws[k][tx * 4];
            const float xv[4] = {xm.x, xm.y, xm.z, xm.w};
            const float wv[4] = {wn.x, wn.y, wn.z, wn.w};
            #pragma unroll
            for (int i = 0; i < 4; ++i)
                #pragma unroll
                for (int j = 0; j < 4; ++j)
                    acc[i][j] += xv[i] * wv[j];
        }
        __syncthreads();
    }

    // epilogue: bias + relu, float4 stores
    float4 bb = *(const float4*)&bias[n0 + tx * 4];
    const float bv[4] = {bb.x, bb.y, bb.z, bb.w};
    #pragma unroll
    for (int i = 0; i < 4; ++i) {
        const int m = m0 + ty * 4 + i;
        float4 o;
        o.x = fmaxf(acc[i][0] + bv[0], 0.0f);
        o.y = fmaxf(acc[i][1] + bv[1], 0.0f);
        o.z = fmaxf(acc[i][2] + bv[2], 0.0f);
        o.w = fmaxf(acc[i][3] + bv[3], 0.0f);
        *(float4*)&out[(size_t)m * 256 + n0 + tx * 4] = o;
    }
}

// ---------------- launch ----------------
extern "C" void kernel_launch(void* const* d_in, const int* in_sizes, int n_in,
                              void* d_out, int out_size)
{
    const float* value = (const float*)d_in[0];
    const float* key_  = (const float*)d_in[1];
    const float* query = (const float*)d_in[2];
    // d_in[3] = mask (unused)
    const float* W_ff  = (const float*)d_in[4];
    const float* b_ff  = (const float*)d_in[5];

    float* out  = (float*)d_out;                         // [2048, 256]
    float* attn = out + (size_t)BATCH * 256;             // [2048, 64, 256]

    cudaFuncSetAttribute(attn_kernel,
                         cudaFuncAttributeMaxDynamicSharedMemorySize,
                         ATTN_SMEM_BYTES);

    attn_kernel<<<BATCH, 256, ATTN_SMEM_BYTES>>>(query, key_, value, attn);

    dim3 grid(BATCH / FBM, 256 / FBN);
    ff_kernel<<<grid, 256>>>(attn, query, W_ff, b_ff, out);
}

// round 3
// speedup vs baseline: 1.3295x; 1.3295x over previous
#include <cuda_runtime.h>
#include <cstdint>
#include <math.h>

#define BATCH 2048
#define TT 64
#define EE 256
#define SCALE 0.125f
#define FK  16384
#define SPLITK 4
#define KSPL (FK / SPLITK)          // 4096

// ------------------------------------------------------------------
// scratch (static __device__ — no allocations allowed)
// ------------------------------------------------------------------
__device__ float g_x[BATCH * TT * EE];              // attn + query (134MB)
__device__ float g_partial[SPLITK * BATCH * 256];   // 8MB

// ------------------------------------------------------------------
// packed f32x2 helpers (FFMA2 — only reachable via PTX fma.rn.f32x2)
// ------------------------------------------------------------------
__device__ __forceinline__ void ffma2(uint64_t& d, uint64_t a, uint64_t b) {
    asm("fma.rn.f32x2 %0, %1, %2, %0;" : "+l"(d) : "l"(a), "l"(b));
}
__device__ __forceinline__ uint64_t dupf(float x) {
    uint64_t d; asm("mov.b64 %0, {%1, %1};" : "=l"(d) : "f"(x)); return d;
}
__device__ __forceinline__ void unpack2(uint64_t d, float& lo, float& hi) {
    asm("mov.b64 {%0, %1}, %2;" : "=f"(lo), "=f"(hi) : "l"(d));
}

// ------------------------------------------------------------------
// attention kernel (+ writes x = attn + query to g_x)
// ------------------------------------------------------------------
#define QT_PITCH 68
#define S_PITCH  65
#define SM_QT (EE * QT_PITCH)
#define SM_KT (EE * QT_PITCH)
#define SM_V  (TT * EE)
#define SM_S  (TT * S_PITCH)
#define ATTN_SMEM_BYTES ((SM_QT + SM_KT + SM_V + SM_S) * 4)

__global__ __launch_bounds__(256, 1)
void attn_kernel(const float* __restrict__ Qg, const float* __restrict__ Kg,
                 const float* __restrict__ Vg, float* __restrict__ Ag)
{
    extern __shared__ float sm[];
    float* QT = sm;
    float* KT = QT + SM_QT;
    float* Vv = KT + SM_KT;
    float* Ss = Vv + SM_V;

    const int tid = threadIdx.x;
    const int b   = blockIdx.x;
    const size_t base = (size_t)b * TT * EE;
    const float* qb = Qg + base;
    const float* kb = Kg + base;
    const float* vb = Vg + base;

    #pragma unroll 4
    for (int i = 0; i < TT; ++i) {
        QT[tid * QT_PITCH + i] = qb[i * EE + tid];
        KT[tid * QT_PITCH + i] = kb[i * EE + tid];
        Vv[i * EE + tid]       = vb[i * EE + tid];
    }
    __syncthreads();

    const int tx = tid & 15;
    const int ty = tid >> 4;

    // ---- S = Q @ K^T : FFMA2, 4 rows x 2 col-pairs per thread ----
    uint64_t acc2[4][2];
    #pragma unroll
    for (int i = 0; i < 4; ++i) { acc2[i][0] = 0ull; acc2[i][1] = 0ull; }

    const float4* QT4 = (const float4*)QT;
    const float4* KT4 = (const float4*)KT;
    #pragma unroll 4
    for (int e = 0; e < EE; ++e) {
        float4 qv = QT4[e * (QT_PITCH / 4) + ty];
        float4 kv = KT4[e * (QT_PITCH / 4) + tx];
        const uint64_t* kp = (const uint64_t*)&kv;
        const float qa[4] = {qv.x, qv.y, qv.z, qv.w};
        #pragma unroll
        for (int i = 0; i < 4; ++i) {
            uint64_t qd = dupf(qa[i]);
            ffma2(acc2[i][0], qd, kp[0]);
            ffma2(acc2[i][1], qd, kp[1]);
        }
    }
    #pragma unroll
    for (int i = 0; i < 4; ++i) {
        float s0, s1, s2, s3;
        unpack2(acc2[i][0], s0, s1);
        unpack2(acc2[i][1], s2, s3);
        float* sr = &Ss[(ty * 4 + i) * S_PITCH + tx * 4];
        sr[0] = s0; sr[1] = s1; sr[2] = s2; sr[3] = s3;
    }
    __syncthreads();

    // ---- softmax ----
    const int warp = tid >> 5, lane = tid & 31;
    #pragma unroll
    for (int rr = 0; rr < 8; ++rr) {
        const int r = warp * 8 + rr;
        float v1 = Ss[r * S_PITCH + lane]      * SCALE;
        float v2 = Ss[r * S_PITCH + lane + 32] * SCALE;
        float m = fmaxf(v1, v2);
        #pragma unroll
        for (int o = 16; o > 0; o >>= 1)
            m = fmaxf(m, __shfl_xor_sync(0xffffffffu, m, o));
        float e1 = expf(v1 - m);
        float e2 = expf(v2 - m);
        float s = e1 + e2;
        #pragma unroll
        for (int o = 16; o > 0; o >>= 1)
            s += __shfl_xor_sync(0xffffffffu, s, o);
        float inv = 1.0f / s;
        Ss[r * S_PITCH + lane]      = e1 * inv;
        Ss[r * S_PITCH + lane + 32] = e2 * inv;
    }
    __syncthreads();

    // ---- A = S @ V : FFMA2, 4 rows x (4 eb x 2 pairs) per thread ----
    uint64_t accA2[4][4][2];
    #pragma unroll
    for (int i = 0; i < 4; ++i)
        #pragma unroll
        for (int eb = 0; eb < 4; ++eb) { accA2[i][eb][0] = 0ull; accA2[i][eb][1] = 0ull; }

    const float4* V4 = (const float4*)Vv;
    #pragma unroll 2
    for (int k = 0; k < TT; ++k) {
        uint64_t vp[4][2];
        #pragma unroll
        for (int eb = 0; eb < 4; ++eb) {
            float4 vv = V4[k * (EE / 4) + eb * 16 + tx];
            const uint64_t* u = (const uint64_t*)&vv;
            vp[eb][0] = u[0]; vp[eb][1] = u[1];
        }
        #pragma unroll
        for (int i = 0; i < 4; ++i) {
            uint64_t sd = dupf(Ss[(ty * 4 + i) * S_PITCH + k]);
            #pragma unroll
            for (int eb = 0; eb < 4; ++eb) {
                ffma2(accA2[i][eb][0], sd, vp[eb][0]);
                ffma2(accA2[i][eb][1], sd, vp[eb][1]);
            }
        }
    }

    float* ab = Ag + base;
    float* xb = g_x + base;
    #pragma unroll
    for (int i = 0; i < 4; ++i) {
        const int qrow = ty * 4 + i;
        #pragma unroll
        for (int eb = 0; eb < 4; ++eb) {
            float4 o;
            unpack2(accA2[i][eb][0], o.x, o.y);
            unpack2(accA2[i][eb][1], o.z, o.w);
            const int e0 = eb * 64 + tx * 4;
            float4 x;
            x.x = o.x + QT[(e0 + 0) * QT_PITCH + qrow];
            x.y = o.y + QT[(e0 + 1) * QT_PITCH + qrow];
            x.z = o.z + QT[(e0 + 2) * QT_PITCH + qrow];
            x.w = o.w + QT[(e0 + 3) * QT_PITCH + qrow];
            *(float4*)&ab[qrow * EE + e0] = o;
            *(float4*)&xb[qrow * EE + e0] = x;
        }
    }
}

// ------------------------------------------------------------------
// FF GEMM: partial[s][m][n] = g_x[m, s-range] @ W^T   (FFMA2 SIMT)
// grid (16, 4, SPLITK), 128 threads, BM=128 BN=64 BK=16, 8x8 thread tile
// ------------------------------------------------------------------
#define FBM 128
#define FBN 64
#define FBK 16
#define NTILE (KSPL / FBK)   // 256

__global__ __launch_bounds__(128, 4)
void ff2_kernel(const float* __restrict__ Wg)
{
    __shared__ float Xs[2][FBK][FBM];
    __shared__ float Ws[2][FBK][FBN];

    const int tid = threadIdx.x;
    const int m0 = blockIdx.x * FBM;
    const int n0 = blockIdx.y * FBN;
    const size_t kbase = (size_t)blockIdx.z * KSPL;

    const float* aptr = g_x + (size_t)(m0 + tid) * FK + kbase;
    const int brow = tid & 63;
    const int bc   = (tid >> 6) * 8;            // 0 or 8
    const float* bptr = Wg + (size_t)(n0 + brow) * FK + kbase + bc;

    const int ty = tid >> 3;   // 0..15 -> rows ty*8..+7
    const int tx = tid & 7;    // cols tx*8..+7

    uint64_t acc[8][4];
    #pragma unroll
    for (int i = 0; i < 8; ++i)
        #pragma unroll
        for (int p = 0; p < 4; ++p) acc[i][p] = 0ull;

    // prologue: stage tile 0
    float4 ax[4], bx[2];
    #pragma unroll
    for (int c = 0; c < 4; ++c) ax[c] = *(const float4*)(aptr + c * 4);
    #pragma unroll
    for (int c = 0; c < 2; ++c) bx[c] = *(const float4*)(bptr + c * 4);

    for (int t = 0; t < NTILE; ++t) {
        const int buf = t & 1;
        // commit staged regs -> smem (transposed to [k][m] / [k][n])
        {
            const float* a = (const float*)ax;
            #pragma unroll
            for (int kk = 0; kk < 16; ++kk) Xs[buf][kk][tid] = a[kk];
            const float* bvv = (const float*)bx;
            #pragma unroll
            for (int kk = 0; kk < 8; ++kk) Ws[buf][bc + kk][brow] = bvv[kk];
        }
        __syncthreads();

        // prefetch next tile
        if (t + 1 < NTILE) {
            const size_t kt = (size_t)(t + 1) * FBK;
            #pragma unroll
            for (int c = 0; c < 4; ++c) ax[c] = *(const float4*)(aptr + kt + c * 4);
            #pragma unroll
            for (int c = 0; c < 2; ++c) bx[c] = *(const float4*)(bptr + kt + c * 4);
        }

        // compute
        #pragma unroll
        for (int k = 0; k < FBK; ++k) {
            float4 a0 = *(const float4*)&Xs[buf][k][ty * 8];
            float4 a1 = *(const float4*)&Xs[buf][k][ty * 8 + 4];
            float4 b0 = *(const float4*)&Ws[buf][k][tx * 8];
            float4 b1 = *(const float4*)&Ws[buf][k][tx * 8 + 4];
            uint64_t bp[4];
            { const uint64_t* u = (const uint64_t*)&b0; bp[0] = u[0]; bp[1] = u[1]; }
            { const uint64_t* u = (const uint64_t*)&b1; bp[2] = u[0]; bp[3] = u[1]; }
            const float aa[8] = {a0.x, a0.y, a0.z, a0.w, a1.x, a1.y, a1.z, a1.w};
            #pragma unroll
            for (int i = 0; i < 8; ++i) {
                uint64_t ad = dupf(aa[i]);
                #pragma unroll
                for (int p = 0; p < 4; ++p) ffma2(acc[i][p], ad, bp[p]);
            }
        }
        __syncthreads();
    }

    // epilogue: unpack and store partials
    #pragma unroll
    for (int i = 0; i < 8; ++i) {
        float c0, c1, c2, c3, c4, c5, c6, c7;
        unpack2(acc[i][0], c0, c1);
        unpack2(acc[i][1], c2, c3);
        unpack2(acc[i][2], c4, c5);
        unpack2(acc[i][3], c6, c7);
        float* prow = g_partial + ((size_t)blockIdx.z * BATCH + m0 + ty * 8 + i) * 256
                      + n0 + tx * 8;
        *(float4*)prow       = make_float4(c0, c1, c2, c3);
        *(float4*)(prow + 4) = make_float4(c4, c5, c6, c7);
    }
}

// ------------------------------------------------------------------
// reduce: out = relu(sum_s partial + bias)
// ------------------------------------------------------------------
__global__ __launch_bounds__(256)
void reduce_kernel(const float* __restrict__ bias, float* __restrict__ out)
{
    const int g = blockIdx.x * 256 + threadIdx.x;   // float4 index
    const int m = g >> 6;
    const int nc = g & 63;
    float4 acc = ((const float4*)bias)[nc];
    #pragma unroll
    for (int ks = 0; ks < SPLITK; ++ks) {
        float4 p = ((const float4*)g_partial)[((size_t)ks * BATCH + m) * 64 + nc];
        acc.x += p.x; acc.y += p.y; acc.z += p.z; acc.w += p.w;
    }
    acc.x = fmaxf(acc.x, 0.0f); acc.y = fmaxf(acc.y, 0.0f);
    acc.z = fmaxf(acc.z, 0.0f); acc.w = fmaxf(acc.w, 0.0f);
    ((float4*)out)[(size_t)m * 64 + nc] = acc;
}

// ------------------------------------------------------------------
// launch
// ------------------------------------------------------------------
extern "C" void kernel_launch(void* const* d_in, const int* in_sizes, int n_in,
                              void* d_out, int out_size)
{
    const float* value = (const float*)d_in[0];
    const float* key_  = (const float*)d_in[1];
    const float* query = (const float*)d_in[2];
    const float* W_ff  = (const float*)d_in[4];
    const float* b_ff  = (const float*)d_in[5];

    float* out  = (float*)d_out;                 // [2048, 256]
    float* attn = out + (size_t)BATCH * 256;     // [2048, 64, 256]

    cudaFuncSetAttribute(attn_kernel,
                         cudaFuncAttributeMaxDynamicSharedMemorySize, ATTN_SMEM_BYTES);

    attn_kernel<<<BATCH, 256, ATTN_SMEM_BYTES>>>(query, key_, value, attn);
    ff2_kernel<<<dim3(16, 4, SPLITK), 128>>>(W_ff);
    reduce_kernel<<<512, 256>>>(b_ff, out);
}